// round 7
// baseline (speedup 1.0000x reference)
#include <cuda_runtime.h>
#include <cuda_bf16.h>
#include <cstdint>
#include <float.h>
#include <math.h>

// Problem constants (b=1 fixed)
#define H    24
#define NSEQ 3072
#define D    128
#define QBLK 192
#define MG   16            // query groups per head
#define NG   (H*MG)        // 384 groups total
#define SCALE 0.08838834764831845f   // 1/sqrt(128)

// ---------------- scratch (device globals; no allocations) ----------------
__device__ float g_S [(size_t)H * NSEQ * NSEQ];          // dense raw scores
__device__ float g_Sc[(size_t)NG * QBLK * NSEQ];         // compact (gathered) scores
__device__ float g_rowmax [H * NSEQ];
__device__ float g_rowsum [H * NSEQ];
__device__ float g_rowmax2[H * NSEQ];
__device__ float g_rowsum2[H * NSEQ];
__device__ float g_cs [NG * NSEQ];
__device__ int   g_idx[NG * NSEQ];
__device__ int   g_cnt[NG];
__device__ int   g_lrmode;   // 0=uint8, 1=int32, 2=float32

// ---------------- smem layout for the dense score kernel ------------------
#define QT_STRIDE 194                 // even -> float2 loads aligned
#define KT_STRIDE 68                  // mult of 4 -> float4 loads aligned
#define SM_QT   0
#define SM_KT   (128 * QT_STRIDE)
#define SMEM1_FLOATS (SM_KT + 128 * KT_STRIDE)
#define SMEM1_BYTES  (SMEM1_FLOATS * 4)

// ---------------- smem layout for the PV kernel ---------------------------
#define PT_STRIDE 194
#define VS_STRIDE 132
#define SM_PT  0
#define SM_VS  (64 * PT_STRIDE)
#define SM_RM2 (SM_VS + 64 * VS_STRIDE)
#define SM_RI2 (SM_RM2 + QBLK)
#define SMEM5_FLOATS (SM_RI2 + QBLK)
#define SMEM5_BYTES  (SMEM5_FLOATS * 4)

// ===========================================================================
// Kernel 0: detect lr_mask storage dtype (scan first 8KB; safe bound).
// ===========================================================================
__global__ void k_detect(const unsigned char* __restrict__ lr)
{
    if (threadIdx.x != 0 || blockIdx.x != 0) return;
    int bad = 0, mis = 0;
    for (int i = 0; i < 8192; ++i) {
        unsigned char b = lr[i];
        if (b > 1) bad++;
        else if (b == 1 && (i & 3)) mis++;
    }
    g_lrmode = bad ? 2 : (mis ? 0 : 1);
}

__device__ __forceinline__ int lr_at(const void* lr, int mode, size_t idx)
{
    if (mode == 0) return ((const unsigned char*)lr)[idx] != 0;
    if (mode == 1) return ((const int*)lr)[idx] != 0;
    return ((const float*)lr)[idx] != 0.f;
}

// ===========================================================================
// Kernel 1: dense scores (exact fp32) for one 192-row group vs all keys;
// writes raw scores to g_S. grid (MG, H), block 256.
// ===========================================================================
__global__ void __launch_bounds__(256)
k_scores(const float* __restrict__ q, const float* __restrict__ kmat)
{
    extern __shared__ float smem[];
    const int m = blockIdx.x, h = blockIdx.y;
    const int r0 = m * QBLK;
    const int tid = threadIdx.x;

    // load Q group, transposed: QT[c][r]
    {
        const float* qg = q + ((size_t)(h * NSEQ + r0)) * D;
        for (int i = tid; i < QBLK * D; i += 256) {
            int r = i >> 7, c = i & 127;
            smem[SM_QT + c * QT_STRIDE + r] = qg[i];
        }
    }
    __syncthreads();

    const int tr = tid & 31, tc = tid >> 5;   // tc in 0..7
    const int rB = 2 * tr;                    // thread rows: 64*i + rB + {0,1}

    for (int t = 0; t < NSEQ / 64; ++t) {
        const int jb = t * 64;
        // load 64 key rows, transposed: KT[c][jr]
        for (int i = tid; i < 64 * D; i += 256) {
            int jr = i >> 7, c = i & 127;
            smem[SM_KT + c * KT_STRIDE + jr] =
                kmat[((size_t)(h * NSEQ + jb + jr)) * D + c];
        }
        __syncthreads();

        float acc[3][2][8];
        #pragma unroll
        for (int i = 0; i < 3; i++)
            #pragma unroll
            for (int s = 0; s < 2; s++)
                #pragma unroll
                for (int j = 0; j < 8; j++) acc[i][s][j] = 0.f;

        #pragma unroll 8
        for (int kk = 0; kk < D; ++kk) {
            float2 a0 = *(const float2*)&smem[SM_QT + kk * QT_STRIDE + rB];
            float2 a1 = *(const float2*)&smem[SM_QT + kk * QT_STRIDE + rB + 64];
            float2 a2 = *(const float2*)&smem[SM_QT + kk * QT_STRIDE + rB + 128];
            float4 b0 = *(const float4*)&smem[SM_KT + kk * KT_STRIDE + tc * 8];
            float4 b1 = *(const float4*)&smem[SM_KT + kk * KT_STRIDE + tc * 8 + 4];
            float bv[8] = {b0.x, b0.y, b0.z, b0.w, b1.x, b1.y, b1.z, b1.w};
            #pragma unroll
            for (int j = 0; j < 8; j++) {
                acc[0][0][j] += a0.x * bv[j];  acc[0][1][j] += a0.y * bv[j];
                acc[1][0][j] += a1.x * bv[j];  acc[1][1][j] += a1.y * bv[j];
                acc[2][0][j] += a2.x * bv[j];  acc[2][1][j] += a2.y * bv[j];
            }
        }

        #pragma unroll
        for (int i = 0; i < 3; i++) {
            #pragma unroll
            for (int s = 0; s < 2; s++) {
                const int row = 64 * i + rB + s;
                size_t base = ((size_t)(h * NSEQ + r0 + row)) * NSEQ + jb + tc * 8;
                *(float4*)&g_S[base]     = make_float4(acc[i][s][0] * SCALE, acc[i][s][1] * SCALE,
                                                       acc[i][s][2] * SCALE, acc[i][s][3] * SCALE);
                *(float4*)&g_S[base + 4] = make_float4(acc[i][s][4] * SCALE, acc[i][s][5] * SCALE,
                                                       acc[i][s][6] * SCALE, acc[i][s][7] * SCALE);
            }
        }
        __syncthreads();
    }
}

// ===========================================================================
// Kernel 1b: per-row max and sumexp over the dense scores, XLA-style:
// one warp per row, lane-strided sequential fp32 accumulation + shuffle tree,
// precise expf. grid (NSEQ/8, H), block 256 (8 warps).
// ===========================================================================
__global__ void __launch_bounds__(256) k_rowstats()
{
    const int h = blockIdx.y;
    const int row = blockIdx.x * 8 + (threadIdx.x >> 5);
    const int lane = threadIdx.x & 31;
    const float* srow = g_S + ((size_t)(h * NSEQ + row)) * NSEQ;

    float mx = -FLT_MAX;
    for (int j = lane; j < NSEQ; j += 32) mx = fmaxf(mx, srow[j]);
    #pragma unroll
    for (int o = 16; o > 0; o >>= 1) mx = fmaxf(mx, __shfl_xor_sync(0xffffffffu, mx, o));

    float sm = 0.f;
    for (int j = lane; j < NSEQ; j += 32) sm += expf(srow[j] - mx);
    #pragma unroll
    for (int o = 16; o > 0; o >>= 1) sm += __shfl_xor_sync(0xffffffffu, sm, o);

    if (lane == 0) {
        g_rowmax[h * NSEQ + row] = mx;
        g_rowsum[h * NSEQ + row] = sm;
    }
}

// ===========================================================================
// Kernel 2: column sums of normalized probs per group: sequential fp32 over
// the 192 rows (matches XLA column-reduce), precise expf, true division.
// grid (MG,H), 256 threads.
// ===========================================================================
__global__ void __launch_bounds__(256) k_colsum()
{
    __shared__ float sm_[QBLK], sz_[QBLK];
    const int m = blockIdx.x, h = blockIdx.y;
    const int r0 = m * QBLK;
    const int tid = threadIdx.x;
    if (tid < QBLK) {
        sm_[tid] = g_rowmax[h * NSEQ + r0 + tid];
        sz_[tid] = g_rowsum[h * NSEQ + r0 + tid];
    }
    __syncthreads();
    float acc[12];
    #pragma unroll
    for (int jj = 0; jj < 12; jj++) acc[jj] = 0.f;
    for (int row = 0; row < QBLK; ++row) {
        size_t base = ((size_t)(h * NSEQ + r0 + row)) * NSEQ;
        float mm = sm_[row], zz = sz_[row];
        #pragma unroll
        for (int jj = 0; jj < 12; jj++)
            acc[jj] += expf(g_S[base + jj * 256 + tid] - mm) / zz;
    }
    size_t cb = (size_t)(h * MG + m) * NSEQ;
    #pragma unroll
    for (int jj = 0; jj < 12; jj++) g_cs[cb + jj * 256 + tid] = acc[jj];
}

// ===========================================================================
// Kernel 3: per-group exact top-K (bitonic sort + strict-greater + index-
// ordered tie fill, replicating lax.top_k) + gate + union lr_mask
// -> compact index list. grid NG, 512 threads.
// ===========================================================================
__global__ void __launch_bounds__(512) k_select(const void* __restrict__ lr,
                                                const void* __restrict__ topkp)
{
    __shared__ float buf[4096];
    __shared__ int eqidx[128];
    __shared__ int lrsum, scnt, sgate, eqcnt, sK;
    __shared__ float sT;
    const int g = blockIdx.x;
    const int tid = threadIdx.x;
    const int mode = g_lrmode;
    const float* cs = g_cs + (size_t)g * NSEQ;
    const size_t lrbase = (size_t)g * NSEQ;

    if (tid == 0) { lrsum = 0; scnt = 0; eqcnt = 0; }
    for (int i = tid; i < 4096; i += 512) buf[i] = (i < NSEQ) ? cs[i] : -FLT_MAX;
    __syncthreads();

    int part = 0;
    for (int i = tid; i < NSEQ; i += 512) part += lr_at(lr, mode, lrbase + i);
    #pragma unroll
    for (int o = 16; o > 0; o >>= 1) part += __shfl_down_sync(0xffffffffu, part, o);
    if ((tid & 31) == 0) atomicAdd(&lrsum, part);

    // ascending bitonic sort of 4096 values
    for (int kk = 2; kk <= 4096; kk <<= 1) {
        for (int j = kk >> 1; j > 0; j >>= 1) {
            __syncthreads();
            for (int i = tid; i < 4096; i += 512) {
                int ixj = i ^ j;
                if (ixj > i) {
                    float a = buf[i], b = buf[ixj];
                    bool up = ((i & kk) == 0);
                    if ((a > b) == up) { buf[i] = b; buf[ixj] = a; }
                }
            }
        }
    }
    __syncthreads();
    if (tid == 0) {
        int K = 512;
        if (topkp) {
            int ri = *((const int*)topkp);
            if (ri >= 1 && ri <= NSEQ) K = ri;
            else {
                float rf = *((const float*)topkp);
                if (rf >= 1.f && rf <= (float)NSEQ) K = (int)rf;
            }
        }
        sK = K;
        sT = buf[4096 - K];                  // K-th largest
        sgate = ((lrsum + K) < NSEQ) ? 1 : 0;
    }
    __syncthreads();
    const float T = sT;
    const int gate = sgate;
    // main pass: lr columns and strictly-greater columns; collect == T cols
    for (int col = tid; col < NSEQ; col += 512) {
        float c = cs[col];
        bool is_lr = lr_at(lr, mode, lrbase + col) != 0;
        bool gt = gate && (c > T);
        if (is_lr || gt) {
            int p = atomicAdd(&scnt, 1);
            g_idx[(size_t)g * NSEQ + p] = col;
        }
        if (gate && (c == T)) {
            int e = atomicAdd(&eqcnt, 1);
            if (e < 128) eqidx[e] = col;
        }
    }
    __syncthreads();
    if (tid == 0) {
        int total = scnt;
        if (gate) {
            // count strictly greater than T from the sorted buffer
            int lo = 0, hi = 4096;
            while (lo < hi) { int mid = (lo + hi) >> 1; if (buf[mid] <= T) lo = mid + 1; else hi = mid; }
            int count_gt = 4096 - lo;
            int need = sK - count_gt;        // >= 1 tie slots, filled by ascending index
            int n = eqcnt < 128 ? eqcnt : 128;
            // insertion sort of tie indices (tiny n)
            for (int i = 1; i < n; i++) {
                int x = eqidx[i], j2 = i - 1;
                while (j2 >= 0 && eqidx[j2] > x) { eqidx[j2 + 1] = eqidx[j2]; j2--; }
                eqidx[j2 + 1] = x;
            }
            for (int i = 0; i < n && need > 0; i++) {
                int col = eqidx[i];
                need--;                       // quota consumed regardless of lr
                if (!lr_at(lr, mode, lrbase + col))
                    g_idx[(size_t)g * NSEQ + total++] = col;
            }
        }
        g_cnt[g] = total;
    }
}

// ===========================================================================
// Kernel 4: gather dense scores at selected columns into compact g_Sc and
// compute per-row (max, sumexp) over the selected set. grid (MG,H), 256 thr.
// ===========================================================================
__global__ void __launch_bounds__(256) k_compact()
{
    __shared__ int sidx[NSEQ];
    const int m = blockIdx.x, h = blockIdx.y;
    const int g = h * MG + m;
    const int r0 = m * QBLK;
    const int tid = threadIdx.x;
    const int cnt = g_cnt[g];

    for (int i = tid; i < cnt; i += 256) sidx[i] = g_idx[(size_t)g * NSEQ + i];
    __syncthreads();

    const int w = tid >> 5, lane = tid & 31;
    for (int row = w; row < QBLK; row += 8) {
        const float* srow = g_S  + ((size_t)(h * NSEQ + r0 + row)) * NSEQ;
        float*       drow = g_Sc + ((size_t)g * QBLK + row) * NSEQ;
        float mx = -FLT_MAX;
        for (int j = lane; j < cnt; j += 32) {
            float s = srow[sidx[j]];
            drow[j] = s;
            mx = fmaxf(mx, s);
        }
        #pragma unroll
        for (int o = 16; o > 0; o >>= 1) mx = fmaxf(mx, __shfl_xor_sync(0xffffffffu, mx, o));
        float sm = 0.f;
        for (int j = lane; j < cnt; j += 32) sm += expf(drow[j] - mx);
        #pragma unroll
        for (int o = 16; o > 0; o >>= 1) sm += __shfl_xor_sync(0xffffffffu, sm, o);
        if (lane == 0) {
            g_rowmax2[h * NSEQ + r0 + row] = mx;
            g_rowsum2[h * NSEQ + r0 + row] = sm;
        }
    }
}

// ===========================================================================
// Kernel 5: O = P @ V over selected columns (exact fp32).
// grid (MG,H), 512 threads.
// ===========================================================================
__global__ void __launch_bounds__(512) k_pv(const float* __restrict__ v, float* __restrict__ o)
{
    extern __shared__ float smem[];
    const int m = blockIdx.x, h = blockIdx.y;
    const int g = h * MG + m;
    const int r0 = m * QBLK;
    const int tid = threadIdx.x;

    if (tid < QBLK) {
        smem[SM_RM2 + tid] = g_rowmax2[h * NSEQ + r0 + tid];
        smem[SM_RI2 + tid] = g_rowsum2[h * NSEQ + r0 + tid];
    }
    const int cnt = g_cnt[g];
    const int nt = (cnt + 63) >> 6;
    __syncthreads();

    const int tr = tid & 31, tc = tid >> 5;   // tc 0..15 -> cols tc*8..+8
    const int rB = 2 * tr;

    float acc[3][2][8];
    #pragma unroll
    for (int i = 0; i < 3; i++)
        #pragma unroll
        for (int s = 0; s < 2; s++)
            #pragma unroll
            for (int j = 0; j < 8; j++) acc[i][s][j] = 0.f;

    for (int t = 0; t < nt; ++t) {
        const int jb = t * 64;
        // gathered V tile
        for (int i = tid; i < 64 * D; i += 512) {
            int jr = i >> 7, c = i & 127;
            int j = jb + jr;
            int col = (j < cnt) ? g_idx[(size_t)g * NSEQ + j] : -1;
            smem[SM_VS + jr * VS_STRIDE + c] =
                (col >= 0) ? v[((size_t)(h * NSEQ + col)) * D + c] : 0.f;
        }
        // probs tile from compact scores, transposed: PT[jj][row]
        for (int i = tid; i < QBLK * 64; i += 512) {
            int row = i >> 6, jj = i & 63;
            int j = jb + jj;
            float p = 0.f;
            if (j < cnt) {
                float s = g_Sc[((size_t)g * QBLK + row) * NSEQ + j];
                p = expf(s - smem[SM_RM2 + row]) / smem[SM_RI2 + row];
            }
            smem[SM_PT + jj * PT_STRIDE + row] = p;
        }
        __syncthreads();

        #pragma unroll 8
        for (int jj = 0; jj < 64; ++jj) {
            float2 a0 = *(const float2*)&smem[SM_PT + jj * PT_STRIDE + rB];
            float2 a1 = *(const float2*)&smem[SM_PT + jj * PT_STRIDE + rB + 64];
            float2 a2 = *(const float2*)&smem[SM_PT + jj * PT_STRIDE + rB + 128];
            float4 b0 = *(const float4*)&smem[SM_VS + jj * VS_STRIDE + tc * 8];
            float4 b1 = *(const float4*)&smem[SM_VS + jj * VS_STRIDE + tc * 8 + 4];
            float bv[8] = {b0.x, b0.y, b0.z, b0.w, b1.x, b1.y, b1.z, b1.w};
            #pragma unroll
            for (int j = 0; j < 8; j++) {
                acc[0][0][j] += a0.x * bv[j];  acc[0][1][j] += a0.y * bv[j];
                acc[1][0][j] += a1.x * bv[j];  acc[1][1][j] += a1.y * bv[j];
                acc[2][0][j] += a2.x * bv[j];  acc[2][1][j] += a2.y * bv[j];
            }
        }
        __syncthreads();
    }

    #pragma unroll
    for (int i = 0; i < 3; i++) {
        #pragma unroll
        for (int s = 0; s < 2; s++) {
            const int row = 64 * i + rB + s;
            size_t base = ((size_t)(h * NSEQ + r0 + row)) * D + tc * 8;
            *(float4*)&o[base]     = make_float4(acc[i][s][0], acc[i][s][1], acc[i][s][2], acc[i][s][3]);
            *(float4*)&o[base + 4] = make_float4(acc[i][s][4], acc[i][s][5], acc[i][s][6], acc[i][s][7]);
        }
    }
}

// ===========================================================================
extern "C" void kernel_launch(void* const* d_in, const int* in_sizes, int n_in,
                              void* d_out, int out_size)
{
    const float* big[3] = {nullptr, nullptr, nullptr};
    int nb = 0;
    const void* lr = nullptr;
    const void* topkp = nullptr;
    for (int i = 0; i < n_in; i++) {
        if (in_sizes[i] == 1) topkp = d_in[i];
        else if (in_sizes[i] == NG * NSEQ) lr = d_in[i];
        else if (nb < 3) big[nb++] = (const float*)d_in[i];
    }
    const float* q = big[0];
    const float* k = big[1];
    const float* v = big[2];
    float* o = (float*)d_out;

    cudaFuncSetAttribute(k_scores, cudaFuncAttributeMaxDynamicSharedMemorySize, SMEM1_BYTES);
    cudaFuncSetAttribute(k_pv,     cudaFuncAttributeMaxDynamicSharedMemorySize, SMEM5_BYTES);

    dim3 gmh(MG, H);
    k_detect<<<1, 32>>>((const unsigned char*)lr);      // lr_mask dtype probe
    k_scores<<<gmh, 256, SMEM1_BYTES>>>(q, k);          // dense scores (fp32)
    k_rowstats<<<dim3(NSEQ / 8, H), 256>>>();           // row max/sumexp (precise)
    k_colsum<<<gmh, 256>>>();                           // per-group column sums
    k_select<<<NG, 512>>>(lr, topkp);                   // exact top-K + lr union
    k_compact<<<gmh, 256>>>();                          // gather scores + sparse row stats
    k_pv<<<gmh, 512, SMEM5_BYTES>>>(v, o);              // P @ V -> output
}

// round 8
// speedup vs baseline: 1.0000x; 1.0000x over previous
#include <cuda_runtime.h>
#include <cuda_bf16.h>
#include <cstdint>
#include <float.h>
#include <math.h>

// Problem constants (b=1 fixed)
#define H    24
#define NSEQ 3072
#define D    128
#define QBLK 192
#define MG   16            // query groups per head
#define NG   (H*MG)        // 384 groups total
#define SCALE 0.08838834764831845f   // 1/sqrt(128)

// ---------------- scratch (device globals; no allocations) ----------------
__device__ float g_S [(size_t)H * NSEQ * NSEQ];          // dense raw scores
__device__ float g_Sc[(size_t)NG * QBLK * NSEQ];         // compact (gathered) scores
__device__ float g_rowmax [H * NSEQ];
__device__ float g_rowsum [H * NSEQ];
__device__ float g_rowmax2[H * NSEQ];
__device__ float g_rowsum2[H * NSEQ];
__device__ float g_cs [NG * NSEQ];
__device__ int   g_idx[NG * NSEQ];
__device__ int   g_cnt[NG];
__device__ int   g_lrmode;   // 0=uint8, 1=int32, 2=float32

// ---------------- smem layout for the dense score kernel ------------------
#define QT_STRIDE 194                 // even -> float2 loads aligned
#define KT_STRIDE 68                  // mult of 4 -> float4 loads aligned
#define SM_QT   0
#define SM_KT   (128 * QT_STRIDE)
#define SMEM1_FLOATS (SM_KT + 128 * KT_STRIDE)
#define SMEM1_BYTES  (SMEM1_FLOATS * 4)

// ---------------- smem layout for the PV kernel ---------------------------
#define PT_STRIDE 194
#define VS_STRIDE 132
#define SM_PT  0
#define SM_VS  (64 * PT_STRIDE)
#define SM_RM2 (SM_VS + 64 * VS_STRIDE)
#define SM_RI2 (SM_RM2 + QBLK)
#define SMEM5_FLOATS (SM_RI2 + QBLK)
#define SMEM5_BYTES  (SMEM5_FLOATS * 4)

// ===========================================================================
// Kernel 0: detect lr_mask storage dtype (scan first 8KB; safe bound).
// ===========================================================================
__global__ void k_detect(const unsigned char* __restrict__ lr)
{
    if (threadIdx.x != 0 || blockIdx.x != 0) return;
    int bad = 0, mis = 0;
    for (int i = 0; i < 8192; ++i) {
        unsigned char b = lr[i];
        if (b > 1) bad++;
        else if (b == 1 && (i & 3)) mis++;
    }
    g_lrmode = bad ? 2 : (mis ? 0 : 1);
}

__device__ __forceinline__ int lr_at(const void* lr, int mode, size_t idx)
{
    if (mode == 0) return ((const unsigned char*)lr)[idx] != 0;
    if (mode == 1) return ((const int*)lr)[idx] != 0;
    return ((const float*)lr)[idx] != 0.f;
}

// ===========================================================================
// Kernel 1: dense scores (exact fp32) for one 192-row group vs all keys;
// writes raw scores to g_S. grid (MG, H), block 256.
// ===========================================================================
__global__ void __launch_bounds__(256)
k_scores(const float* __restrict__ q, const float* __restrict__ kmat)
{
    extern __shared__ float smem[];
    const int m = blockIdx.x, h = blockIdx.y;
    const int r0 = m * QBLK;
    const int tid = threadIdx.x;

    // load Q group, transposed: QT[c][r]
    {
        const float* qg = q + ((size_t)(h * NSEQ + r0)) * D;
        for (int i = tid; i < QBLK * D; i += 256) {
            int r = i >> 7, c = i & 127;
            smem[SM_QT + c * QT_STRIDE + r] = qg[i];
        }
    }
    __syncthreads();

    const int tr = tid & 31, tc = tid >> 5;   // tc in 0..7
    const int rB = 2 * tr;                    // thread rows: 64*i + rB + {0,1}

    for (int t = 0; t < NSEQ / 64; ++t) {
        const int jb = t * 64;
        // load 64 key rows, transposed: KT[c][jr]
        for (int i = tid; i < 64 * D; i += 256) {
            int jr = i >> 7, c = i & 127;
            smem[SM_KT + c * KT_STRIDE + jr] =
                kmat[((size_t)(h * NSEQ + jb + jr)) * D + c];
        }
        __syncthreads();

        float acc[3][2][8];
        #pragma unroll
        for (int i = 0; i < 3; i++)
            #pragma unroll
            for (int s = 0; s < 2; s++)
                #pragma unroll
                for (int j = 0; j < 8; j++) acc[i][s][j] = 0.f;

        #pragma unroll 8
        for (int kk = 0; kk < D; ++kk) {
            float2 a0 = *(const float2*)&smem[SM_QT + kk * QT_STRIDE + rB];
            float2 a1 = *(const float2*)&smem[SM_QT + kk * QT_STRIDE + rB + 64];
            float2 a2 = *(const float2*)&smem[SM_QT + kk * QT_STRIDE + rB + 128];
            float4 b0 = *(const float4*)&smem[SM_KT + kk * KT_STRIDE + tc * 8];
            float4 b1 = *(const float4*)&smem[SM_KT + kk * KT_STRIDE + tc * 8 + 4];
            float bv[8] = {b0.x, b0.y, b0.z, b0.w, b1.x, b1.y, b1.z, b1.w};
            #pragma unroll
            for (int j = 0; j < 8; j++) {
                acc[0][0][j] += a0.x * bv[j];  acc[0][1][j] += a0.y * bv[j];
                acc[1][0][j] += a1.x * bv[j];  acc[1][1][j] += a1.y * bv[j];
                acc[2][0][j] += a2.x * bv[j];  acc[2][1][j] += a2.y * bv[j];
            }
        }

        #pragma unroll
        for (int i = 0; i < 3; i++) {
            #pragma unroll
            for (int s = 0; s < 2; s++) {
                const int row = 64 * i + rB + s;
                size_t base = ((size_t)(h * NSEQ + r0 + row)) * NSEQ + jb + tc * 8;
                *(float4*)&g_S[base]     = make_float4(acc[i][s][0] * SCALE, acc[i][s][1] * SCALE,
                                                       acc[i][s][2] * SCALE, acc[i][s][3] * SCALE);
                *(float4*)&g_S[base + 4] = make_float4(acc[i][s][4] * SCALE, acc[i][s][5] * SCALE,
                                                       acc[i][s][6] * SCALE, acc[i][s][7] * SCALE);
            }
        }
        __syncthreads();
    }
}

// ===========================================================================
// Kernel 1b: per-row max and sumexp over the dense scores, XLA-style:
// one warp per row, lane-strided sequential fp32 accumulation + shuffle tree,
// precise expf. grid (NSEQ/8, H), block 256 (8 warps).
// ===========================================================================
__global__ void __launch_bounds__(256) k_rowstats()
{
    const int h = blockIdx.y;
    const int row = blockIdx.x * 8 + (threadIdx.x >> 5);
    const int lane = threadIdx.x & 31;
    const float* srow = g_S + ((size_t)(h * NSEQ + row)) * NSEQ;

    float mx = -FLT_MAX;
    for (int j = lane; j < NSEQ; j += 32) mx = fmaxf(mx, srow[j]);
    #pragma unroll
    for (int o = 16; o > 0; o >>= 1) mx = fmaxf(mx, __shfl_xor_sync(0xffffffffu, mx, o));

    float sm = 0.f;
    for (int j = lane; j < NSEQ; j += 32) sm += expf(srow[j] - mx);
    #pragma unroll
    for (int o = 16; o > 0; o >>= 1) sm += __shfl_xor_sync(0xffffffffu, sm, o);

    if (lane == 0) {
        g_rowmax[h * NSEQ + row] = mx;
        g_rowsum[h * NSEQ + row] = sm;
    }
}

// ===========================================================================
// Kernel 2: column sums of normalized probs per group: sequential fp32 over
// the 192 rows (matches XLA column-reduce), precise expf, true division.
// grid (MG,H), 256 threads.
// ===========================================================================
__global__ void __launch_bounds__(256) k_colsum()
{
    __shared__ float sm_[QBLK], sz_[QBLK];
    const int m = blockIdx.x, h = blockIdx.y;
    const int r0 = m * QBLK;
    const int tid = threadIdx.x;
    if (tid < QBLK) {
        sm_[tid] = g_rowmax[h * NSEQ + r0 + tid];
        sz_[tid] = g_rowsum[h * NSEQ + r0 + tid];
    }
    __syncthreads();
    float acc[12];
    #pragma unroll
    for (int jj = 0; jj < 12; jj++) acc[jj] = 0.f;
    for (int row = 0; row < QBLK; ++row) {
        size_t base = ((size_t)(h * NSEQ + r0 + row)) * NSEQ;
        float mm = sm_[row], zz = sz_[row];
        #pragma unroll
        for (int jj = 0; jj < 12; jj++)
            acc[jj] += expf(g_S[base + jj * 256 + tid] - mm) / zz;
    }
    size_t cb = (size_t)(h * MG + m) * NSEQ;
    #pragma unroll
    for (int jj = 0; jj < 12; jj++) g_cs[cb + jj * 256 + tid] = acc[jj];
}

// ===========================================================================
// Kernel 3: per-group exact top-K (bitonic sort + strict-greater + index-
// ordered tie fill, replicating lax.top_k) + gate + union lr_mask
// -> compact index list. grid NG, 512 threads.
// ===========================================================================
__global__ void __launch_bounds__(512) k_select(const void* __restrict__ lr,
                                                const void* __restrict__ topkp)
{
    __shared__ float buf[4096];
    __shared__ int eqidx[128];
    __shared__ int lrsum, scnt, sgate, eqcnt, sK;
    __shared__ float sT;
    const int g = blockIdx.x;
    const int tid = threadIdx.x;
    const int mode = g_lrmode;
    const float* cs = g_cs + (size_t)g * NSEQ;
    const size_t lrbase = (size_t)g * NSEQ;

    if (tid == 0) { lrsum = 0; scnt = 0; eqcnt = 0; }
    for (int i = tid; i < 4096; i += 512) buf[i] = (i < NSEQ) ? cs[i] : -FLT_MAX;
    __syncthreads();

    int part = 0;
    for (int i = tid; i < NSEQ; i += 512) part += lr_at(lr, mode, lrbase + i);
    #pragma unroll
    for (int o = 16; o > 0; o >>= 1) part += __shfl_down_sync(0xffffffffu, part, o);
    if ((tid & 31) == 0) atomicAdd(&lrsum, part);

    // ascending bitonic sort of 4096 values
    for (int kk = 2; kk <= 4096; kk <<= 1) {
        for (int j = kk >> 1; j > 0; j >>= 1) {
            __syncthreads();
            for (int i = tid; i < 4096; i += 512) {
                int ixj = i ^ j;
                if (ixj > i) {
                    float a = buf[i], b = buf[ixj];
                    bool up = ((i & kk) == 0);
                    if ((a > b) == up) { buf[i] = b; buf[ixj] = a; }
                }
            }
        }
    }
    __syncthreads();
    if (tid == 0) {
        int K = 512;
        if (topkp) {
            int ri = *((const int*)topkp);
            if (ri >= 1 && ri <= NSEQ) K = ri;
            else {
                float rf = *((const float*)topkp);
                if (rf >= 1.f && rf <= (float)NSEQ) K = (int)rf;
            }
        }
        sK = K;
        sT = buf[4096 - K];                  // K-th largest
        sgate = ((lrsum + K) < NSEQ) ? 1 : 0;
    }
    __syncthreads();
    const float T = sT;
    const int gate = sgate;
    // main pass: lr columns and strictly-greater columns; collect == T cols
    for (int col = tid; col < NSEQ; col += 512) {
        float c = cs[col];
        bool is_lr = lr_at(lr, mode, lrbase + col) != 0;
        bool gt = gate && (c > T);
        if (is_lr || gt) {
            int p = atomicAdd(&scnt, 1);
            g_idx[(size_t)g * NSEQ + p] = col;
        }
        if (gate && (c == T)) {
            int e = atomicAdd(&eqcnt, 1);
            if (e < 128) eqidx[e] = col;
        }
    }
    __syncthreads();
    if (tid == 0) {
        int total = scnt;
        if (gate) {
            // count strictly greater than T from the sorted buffer
            int lo = 0, hi = 4096;
            while (lo < hi) { int mid = (lo + hi) >> 1; if (buf[mid] <= T) lo = mid + 1; else hi = mid; }
            int count_gt = 4096 - lo;
            int need = sK - count_gt;        // >= 1 tie slots, filled by ascending index
            int n = eqcnt < 128 ? eqcnt : 128;
            // insertion sort of tie indices (tiny n)
            for (int i = 1; i < n; i++) {
                int x = eqidx[i], j2 = i - 1;
                while (j2 >= 0 && eqidx[j2] > x) { eqidx[j2 + 1] = eqidx[j2]; j2--; }
                eqidx[j2 + 1] = x;
            }
            for (int i = 0; i < n && need > 0; i++) {
                int col = eqidx[i];
                need--;                       // quota consumed regardless of lr
                if (!lr_at(lr, mode, lrbase + col))
                    g_idx[(size_t)g * NSEQ + total++] = col;
            }
        }
        g_cnt[g] = total;
    }
}

// ===========================================================================
// Kernel 4: gather dense scores at selected columns into compact g_Sc and
// compute per-row (max, sumexp) over the selected set. grid (MG,H), 256 thr.
// ===========================================================================
__global__ void __launch_bounds__(256) k_compact()
{
    __shared__ int sidx[NSEQ];
    const int m = blockIdx.x, h = blockIdx.y;
    const int g = h * MG + m;
    const int r0 = m * QBLK;
    const int tid = threadIdx.x;
    const int cnt = g_cnt[g];

    for (int i = tid; i < cnt; i += 256) sidx[i] = g_idx[(size_t)g * NSEQ + i];
    __syncthreads();

    const int w = tid >> 5, lane = tid & 31;
    for (int row = w; row < QBLK; row += 8) {
        const float* srow = g_S  + ((size_t)(h * NSEQ + r0 + row)) * NSEQ;
        float*       drow = g_Sc + ((size_t)g * QBLK + row) * NSEQ;
        float mx = -FLT_MAX;
        for (int j = lane; j < cnt; j += 32) {
            float s = srow[sidx[j]];
            drow[j] = s;
            mx = fmaxf(mx, s);
        }
        #pragma unroll
        for (int o = 16; o > 0; o >>= 1) mx = fmaxf(mx, __shfl_xor_sync(0xffffffffu, mx, o));
        float sm = 0.f;
        for (int j = lane; j < cnt; j += 32) sm += expf(drow[j] - mx);
        #pragma unroll
        for (int o = 16; o > 0; o >>= 1) sm += __shfl_xor_sync(0xffffffffu, sm, o);
        if (lane == 0) {
            g_rowmax2[h * NSEQ + r0 + row] = mx;
            g_rowsum2[h * NSEQ + r0 + row] = sm;
        }
    }
}

// ===========================================================================
// Kernel 5: O = P @ V over selected columns (exact fp32).
// grid (MG,H), 512 threads.
// ===========================================================================
__global__ void __launch_bounds__(512) k_pv(const float* __restrict__ v, float* __restrict__ o)
{
    extern __shared__ float smem[];
    const int m = blockIdx.x, h = blockIdx.y;
    const int g = h * MG + m;
    const int r0 = m * QBLK;
    const int tid = threadIdx.x;

    if (tid < QBLK) {
        smem[SM_RM2 + tid] = g_rowmax2[h * NSEQ + r0 + tid];
        smem[SM_RI2 + tid] = g_rowsum2[h * NSEQ + r0 + tid];
    }
    const int cnt = g_cnt[g];
    const int nt = (cnt + 63) >> 6;
    __syncthreads();

    const int tr = tid & 31, tc = tid >> 5;   // tc 0..15 -> cols tc*8..+8
    const int rB = 2 * tr;

    float acc[3][2][8];
    #pragma unroll
    for (int i = 0; i < 3; i++)
        #pragma unroll
        for (int s = 0; s < 2; s++)
            #pragma unroll
            for (int j = 0; j < 8; j++) acc[i][s][j] = 0.f;

    for (int t = 0; t < nt; ++t) {
        const int jb = t * 64;
        // gathered V tile
        for (int i = tid; i < 64 * D; i += 512) {
            int jr = i >> 7, c = i & 127;
            int j = jb + jr;
            int col = (j < cnt) ? g_idx[(size_t)g * NSEQ + j] : -1;
            smem[SM_VS + jr * VS_STRIDE + c] =
                (col >= 0) ? v[((size_t)(h * NSEQ + col)) * D + c] : 0.f;
        }
        // probs tile from compact scores, transposed: PT[jj][row]
        for (int i = tid; i < QBLK * 64; i += 512) {
            int row = i >> 6, jj = i & 63;
            int j = jb + jj;
            float p = 0.f;
            if (j < cnt) {
                float s = g_Sc[((size_t)g * QBLK + row) * NSEQ + j];
                p = expf(s - smem[SM_RM2 + row]) / smem[SM_RI2 + row];
            }
            smem[SM_PT + jj * PT_STRIDE + row] = p;
        }
        __syncthreads();

        #pragma unroll 8
        for (int jj = 0; jj < 64; ++jj) {
            float2 a0 = *(const float2*)&smem[SM_PT + jj * PT_STRIDE + rB];
            float2 a1 = *(const float2*)&smem[SM_PT + jj * PT_STRIDE + rB + 64];
            float2 a2 = *(const float2*)&smem[SM_PT + jj * PT_STRIDE + rB + 128];
            float4 b0 = *(const float4*)&smem[SM_VS + jj * VS_STRIDE + tc * 8];
            float4 b1 = *(const float4*)&smem[SM_VS + jj * VS_STRIDE + tc * 8 + 4];
            float bv[8] = {b0.x, b0.y, b0.z, b0.w, b1.x, b1.y, b1.z, b1.w};
            #pragma unroll
            for (int j = 0; j < 8; j++) {
                acc[0][0][j] += a0.x * bv[j];  acc[0][1][j] += a0.y * bv[j];
                acc[1][0][j] += a1.x * bv[j];  acc[1][1][j] += a1.y * bv[j];
                acc[2][0][j] += a2.x * bv[j];  acc[2][1][j] += a2.y * bv[j];
            }
        }
        __syncthreads();
    }

    #pragma unroll
    for (int i = 0; i < 3; i++) {
        #pragma unroll
        for (int s = 0; s < 2; s++) {
            const int row = 64 * i + rB + s;
            size_t base = ((size_t)(h * NSEQ + r0 + row)) * D + tc * 8;
            *(float4*)&o[base]     = make_float4(acc[i][s][0], acc[i][s][1], acc[i][s][2], acc[i][s][3]);
            *(float4*)&o[base + 4] = make_float4(acc[i][s][4], acc[i][s][5], acc[i][s][6], acc[i][s][7]);
        }
    }
}

// ===========================================================================
extern "C" void kernel_launch(void* const* d_in, const int* in_sizes, int n_in,
                              void* d_out, int out_size)
{
    const float* big[3] = {nullptr, nullptr, nullptr};
    int nb = 0;
    const void* lr = nullptr;
    const void* topkp = nullptr;
    for (int i = 0; i < n_in; i++) {
        if (in_sizes[i] == 1) topkp = d_in[i];
        else if (in_sizes[i] == NG * NSEQ) lr = d_in[i];
        else if (nb < 3) big[nb++] = (const float*)d_in[i];
    }
    const float* q = big[0];
    const float* k = big[1];
    const float* v = big[2];
    float* o = (float*)d_out;

    cudaFuncSetAttribute(k_scores, cudaFuncAttributeMaxDynamicSharedMemorySize, SMEM1_BYTES);
    cudaFuncSetAttribute(k_pv,     cudaFuncAttributeMaxDynamicSharedMemorySize, SMEM5_BYTES);

    dim3 gmh(MG, H);
    k_detect<<<1, 32>>>((const unsigned char*)lr);      // lr_mask dtype probe
    k_scores<<<gmh, 256, SMEM1_BYTES>>>(q, k);          // dense scores (fp32)
    k_rowstats<<<dim3(NSEQ / 8, H), 256>>>();           // row max/sumexp (precise)
    k_colsum<<<gmh, 256>>>();                           // per-group column sums
    k_select<<<NG, 512>>>(lr, topkp);                   // exact top-K + lr union
    k_compact<<<gmh, 256>>>();                          // gather scores + sparse row stats
    k_pv<<<gmh, 512, SMEM5_BYTES>>>(v, o);              // P @ V -> output
}